// round 1
// baseline (speedup 1.0000x reference)
#include <cuda_runtime.h>

// Problem constants (shapes are fixed by the dataset).
#define C_DIM 64
#define HW 32
#define PTS_PER_BLK 128
#define TPB 256

// Planes transposed to [plane][y][x][c] so each bilinear corner is a
// contiguous 64-float (256 B) vector. 3 * 32 * 32 * 64 * 4B = 768 KB.
__device__ float g_planesT[3 * HW * HW * C_DIM];

__global__ void transpose_planes_k(const float* __restrict__ pxy,
                                   const float* __restrict__ pyz,
                                   const float* __restrict__ pxz) {
    int idx = blockIdx.x * blockDim.x + threadIdx.x; // [plane][y][x][c], c fastest
    if (idx >= 3 * HW * HW * C_DIM) return;
    int c = idx & (C_DIM - 1);
    int r = idx >> 6;          // plane*1024 + y*32 + x
    int plane = r >> 10;
    int yx = r & 1023;
    const float* src = (plane == 0) ? pxy : ((plane == 1) ? pyz : pxz);
    g_planesT[idx] = src[c * (HW * HW) + yx];   // coalesced store, L2-hot gather
}

// Fused: sample 3 planes -> features -> 64->128 relu -> 128->128 relu -> 128->1.
// Block = 128 points, 256 threads arranged (tx = point-lane 0..15, ty = unit-lane 0..15).
// Each thread owns an 8x8 register tile (8 points stride 16, 8 units stride 16).
//
// Shared layout (floats):
//   region A [0 .. 16896):  Fs[64][136] (0..8704) + W1s[64][128] (8704..16896)
//                           reused later as W2s[128][128], then as red[128][17]
//   region B [16896..34304): Hs[128][136]
//   region C [34304..34688): b1s[128], b2s[128], w3s[128]
__global__ __launch_bounds__(TPB) void fused_k(
    const float* __restrict__ coords,
    const float* __restrict__ w1, const float* __restrict__ b1,
    const float* __restrict__ w2, const float* __restrict__ b2,
    const float* __restrict__ w3, const float* __restrict__ b3,
    float* __restrict__ out)
{
    extern __shared__ float sm[];
    float* Fs  = sm;            // [64][136]  (c-major, point stride 1)
    float* W1s = sm + 8704;     // [64][128]  (c-major, unit stride 1)
    float* W2s = sm;            // [128][128] (k-major) -- reuses region A
    float* Hs  = sm + 16896;    // [128][136] (unit-major, point stride 1)
    float* b1s = sm + 34304;
    float* b2s = sm + 34432;
    float* w3s = sm + 34560;
    float* red = sm;            // [128][17]  -- reuses region A at the end

    const int tid = threadIdx.x;
    const int tx = tid & 15;    // point lane
    const int ty = tid >> 4;    // unit lane

    // ---- stage W1 (transposed to [c][o]) and small vectors --------------------
    for (int i = tid; i < 64 * 128; i += TPB) {
        int c = i >> 7, o = i & 127;
        W1s[i] = w1[o * 64 + c];      // coalesced smem store; strided L2-hot load
    }
    if (tid < 128) {
        b1s[tid] = b1[tid];
        b2s[tid] = b2[tid];
        w3s[tid] = w3[tid];
    }

    // ---- sampling: thread handles point p = tid>>1, channel half (tid&1)*32 ---
    {
        const int p   = tid >> 1;
        const int ch0 = (tid & 1) * 32;
        const int gp  = blockIdx.x * PTS_PER_BLK + p;
        const float cx = coords[gp * 3 + 0];
        const float cy = coords[gp * 3 + 1];
        const float cz = coords[gp * 3 + 2];

        float featr[32];
        #pragma unroll
        for (int e = 0; e < 32; e++) featr[e] = 1.0f;

        const float us[3] = {cx, cy, cx};   // xy:(x,y)  yz:(y,z)  xz:(x,z)
        const float vs[3] = {cy, cz, cz};

        #pragma unroll
        for (int pl = 0; pl < 3; pl++) {
            // align_corners=True mapping
            float fx = (us[pl] + 1.0f) * 0.5f * (float)(HW - 1);
            float fy = (vs[pl] + 1.0f) * 0.5f * (float)(HW - 1);
            float x0f = floorf(fx), y0f = floorf(fy);
            int x0 = (int)x0f, y0 = (int)y0f;
            float wx1 = fx - x0f, wy1 = fy - y0f;
            float wx0 = 1.0f - wx1, wy0 = 1.0f - wy1;
            bool vx0 = (x0 >= 0) && (x0 < HW);
            bool vx1 = (x0 + 1 >= 0) && (x0 + 1 < HW);
            bool vy0 = (y0 >= 0) && (y0 < HW);
            bool vy1 = (y0 + 1 >= 0) && (y0 + 1 < HW);
            float w00 = (vx0 && vy0) ? wx0 * wy0 : 0.0f;
            float w10 = (vx1 && vy0) ? wx1 * wy0 : 0.0f;
            float w01 = (vx0 && vy1) ? wx0 * wy1 : 0.0f;
            float w11 = (vx1 && vy1) ? wx1 * wy1 : 0.0f;
            int x0c = min(max(x0, 0), HW - 1);
            int x1c = min(max(x0 + 1, 0), HW - 1);
            int y0c = min(max(y0, 0), HW - 1);
            int y1c = min(max(y0 + 1, 0), HW - 1);

            const float* base = g_planesT + pl * (HW * HW * C_DIM) + ch0;
            const float4* p00 = (const float4*)(base + (y0c * HW + x0c) * C_DIM);
            const float4* p10 = (const float4*)(base + (y0c * HW + x1c) * C_DIM);
            const float4* p01 = (const float4*)(base + (y1c * HW + x0c) * C_DIM);
            const float4* p11 = (const float4*)(base + (y1c * HW + x1c) * C_DIM);

            #pragma unroll
            for (int cc = 0; cc < 8; cc++) {
                float4 a = p00[cc], b = p10[cc], d = p01[cc], e = p11[cc];
                featr[cc * 4 + 0] *= w00 * a.x + w10 * b.x + w01 * d.x + w11 * e.x;
                featr[cc * 4 + 1] *= w00 * a.y + w10 * b.y + w01 * d.y + w11 * e.y;
                featr[cc * 4 + 2] *= w00 * a.z + w10 * b.z + w01 * d.z + w11 * e.z;
                featr[cc * 4 + 3] *= w00 * a.w + w10 * b.w + w01 * d.w + w11 * e.w;
            }
        }

        #pragma unroll
        for (int e = 0; e < 32; e++)
            Fs[(ch0 + e) * 136 + p] = featr[e];
    }
    __syncthreads();

    // ---- layer 1: H[o][p] = relu(sum_c F[c][p] * W1[c][o] + b1[o]) -----------
    float acc[8][8];
    #pragma unroll
    for (int j = 0; j < 8; j++)
        #pragma unroll
        for (int i = 0; i < 8; i++) acc[j][i] = 0.0f;

    #pragma unroll 8
    for (int c = 0; c < 64; c++) {
        float a[8], b[8];
        #pragma unroll
        for (int i = 0; i < 8; i++) a[i] = Fs[c * 136 + tx + 16 * i];
        #pragma unroll
        for (int j = 0; j < 8; j++) b[j] = W1s[c * 128 + ty + 16 * j];
        #pragma unroll
        for (int j = 0; j < 8; j++)
            #pragma unroll
            for (int i = 0; i < 8; i++)
                acc[j][i] += a[i] * b[j];
    }
    #pragma unroll
    for (int j = 0; j < 8; j++) {
        int o = ty + 16 * j;
        float bb = b1s[o];
        #pragma unroll
        for (int i = 0; i < 8; i++)
            Hs[o * 136 + tx + 16 * i] = fmaxf(acc[j][i] + bb, 0.0f);
    }
    __syncthreads();   // region A (Fs/W1s) now dead -> reuse for W2s

    // ---- stage W2 (transposed to [k][o]) -------------------------------------
    for (int i = tid; i < 128 * 128; i += TPB) {
        int k = i >> 7, o = i & 127;
        W2s[i] = w2[o * 128 + k];
    }
    __syncthreads();

    // ---- layer 2 + layer 3 ----------------------------------------------------
    #pragma unroll
    for (int j = 0; j < 8; j++)
        #pragma unroll
        for (int i = 0; i < 8; i++) acc[j][i] = 0.0f;

    #pragma unroll 8
    for (int k = 0; k < 128; k++) {
        float a[8], b[8];
        #pragma unroll
        for (int i = 0; i < 8; i++) a[i] = Hs[k * 136 + tx + 16 * i];
        #pragma unroll
        for (int j = 0; j < 8; j++) b[j] = W2s[k * 128 + ty + 16 * j];
        #pragma unroll
        for (int j = 0; j < 8; j++)
            #pragma unroll
            for (int i = 0; i < 8; i++)
                acc[j][i] += a[i] * b[j];
    }

    float pout[8];
    #pragma unroll
    for (int i = 0; i < 8; i++) pout[i] = 0.0f;
    #pragma unroll
    for (int j = 0; j < 8; j++) {
        int o = ty + 16 * j;
        float bb = b2s[o];
        float wv = w3s[o];
        #pragma unroll
        for (int i = 0; i < 8; i++)
            pout[i] += fmaxf(acc[j][i] + bb, 0.0f) * wv;
    }

    __syncthreads();   // everyone done reading W2s -> reuse region A as red
    #pragma unroll
    for (int i = 0; i < 8; i++)
        red[(tx + 16 * i) * 17 + ty] = pout[i];
    __syncthreads();

    if (tid < PTS_PER_BLK) {
        float s = 0.0f;
        #pragma unroll
        for (int j = 0; j < 16; j++) s += red[tid * 17 + j];
        out[blockIdx.x * PTS_PER_BLK + tid] = s + b3[0];
    }
}

extern "C" void kernel_launch(void* const* d_in, const int* in_sizes, int n_in,
                              void* d_out, int out_size) {
    const float* coords = (const float*)d_in[0];
    const float* pxy    = (const float*)d_in[1];
    const float* pyz    = (const float*)d_in[2];
    const float* pxz    = (const float*)d_in[3];
    const float* w1     = (const float*)d_in[4];
    const float* b1     = (const float*)d_in[5];
    const float* w2     = (const float*)d_in[6];
    const float* b2     = (const float*)d_in[7];
    const float* w3     = (const float*)d_in[8];
    const float* b3     = (const float*)d_in[9];
    float* out = (float*)d_out;

    const int M = in_sizes[0] / 3;   // 1048576

    transpose_planes_k<<<(3 * HW * HW * C_DIM + 255) / 256, 256>>>(pxy, pyz, pxz);

    const size_t smem_bytes = 34688 * sizeof(float);  // 138,752 B
    cudaFuncSetAttribute(fused_k, cudaFuncAttributeMaxDynamicSharedMemorySize,
                         (int)smem_bytes);
    fused_k<<<M / PTS_PER_BLK, TPB, smem_bytes>>>(coords, w1, b1, w2, b2, w3, b3, out);
}

// round 4
// speedup vs baseline: 1.3251x; 1.3251x over previous
#include <cuda_runtime.h>

// Problem constants (shapes are fixed by the dataset).
#define C_DIM 64
#define HW 32
#define PTS_PER_BLK 128
#define TPB 512

// Planes transposed to [plane][y][x][c]: each bilinear corner is a contiguous
// 64-float (256 B) vector. 3 * 32 * 32 * 64 * 4B = 768 KB (L2-resident).
__device__ float g_planesT[3 * HW * HW * C_DIM];

__global__ void transpose_planes_k(const float* __restrict__ pxy,
                                   const float* __restrict__ pyz,
                                   const float* __restrict__ pxz) {
    int idx = blockIdx.x * blockDim.x + threadIdx.x; // [plane][y][x][c], c fastest
    if (idx >= 3 * HW * HW * C_DIM) return;
    int c = idx & (C_DIM - 1);
    int r = idx >> 6;          // plane*1024 + y*32 + x
    int plane = r >> 10;
    int yx = r & 1023;
    const float* src = (plane == 0) ? pxy : ((plane == 1) ? pyz : pxz);
    g_planesT[idx] = src[c * (HW * HW) + yx];
}

// ---- packed fp32x2 helpers (Blackwell dual-FP32 path) ----------------------
__device__ __forceinline__ unsigned long long ffma2(unsigned long long a,
                                                    unsigned long long b,
                                                    unsigned long long c) {
    unsigned long long d;
    asm("fma.rn.f32x2 %0, %1, %2, %3;" : "=l"(d) : "l"(a), "l"(b), "l"(c));
    return d;
}
__device__ __forceinline__ unsigned long long bcast2(float v) {
    unsigned long long d;
    unsigned int r = __float_as_uint(v);
    asm("mov.b64 %0, {%1, %1};" : "=l"(d) : "r"(r));
    return d;
}
__device__ __forceinline__ void unpack2(unsigned long long v, float& lo, float& hi) {
    unsigned int a, b;
    asm("mov.b64 {%0, %1}, %2;" : "=r"(a), "=r"(b) : "l"(v));
    lo = __uint_as_float(a);
    hi = __uint_as_float(b);
}

// Shared layout (floats):
//   region A [0 .. 16768): Fs[64][132] (0..8448) + W1s[128][65] (8448..16768)
//                          reused as W2s[128][65] (half-k stage), then red[128][33]
//   region B [16768 .. 33664): Hs[128][132]
//   region C [33664 .. 34048): b1s[128], b2s[128], w3s[128]
// Total 34048 floats = 136,192 B -> 1 CTA/SM, 16 warps.
#define FS_OFF   0
#define W1_OFF   8448
#define W2_OFF   8448      /* reuses W1s slot after layer 1 */
#define HS_OFF   16768
#define B1_OFF   33664
#define B2_OFF   33792
#define W3_OFF   33920
#define SMEM_FL  34048

// Thread tile: tx = tid&15 -> 8 points {4tx..4tx+3, 64+4tx..64+4tx+3}
//              ty = tid>>4 (0..31) -> 4 units {4ty..4ty+3}
__global__ __launch_bounds__(TPB, 1) void fused_k(
    const float* __restrict__ coords,
    const float* __restrict__ w1, const float* __restrict__ b1,
    const float* __restrict__ w2, const float* __restrict__ b2,
    const float* __restrict__ w3, const float* __restrict__ b3,
    float* __restrict__ out)
{
    extern __shared__ float sm[];
    float* Fs  = sm + FS_OFF;   // [64][132]  c-major, point stride 1
    float* W1s = sm + W1_OFF;   // [128][65]  o-major (gmem layout, padded)
    float* W2s = sm + W2_OFF;   // [128][65]  o-major half-k stage
    float* Hs  = sm + HS_OFF;   // [128][132] unit-major, point stride 1
    float* b1s = sm + B1_OFF;
    float* b2s = sm + B2_OFF;
    float* w3s = sm + W3_OFF;
    float* red = sm;            // [128][33]  reuses region A at the end

    const int tid = threadIdx.x;
    const int tx = tid & 15;
    const int ty = tid >> 4;

    // ---- stage W1 (same o-major layout as gmem, rows padded to 65) ----------
    for (int i = tid; i < 128 * 64; i += TPB) {
        int o = i >> 6, c = i & 63;
        W1s[o * 65 + c] = w1[i];           // fully coalesced gmem read
    }
    if (tid < 128) {
        b1s[tid] = b1[tid];
        b2s[tid] = b2[tid];
        w3s[tid] = w3[tid];
    }

    // ---- sampling: 4 threads per point; p = tid&127, 16 channels each -------
    {
        const int p   = tid & 127;
        const int ch0 = (tid >> 7) * 16;
        const int gp  = blockIdx.x * PTS_PER_BLK + p;
        const float cx = coords[gp * 3 + 0];
        const float cy = coords[gp * 3 + 1];
        const float cz = coords[gp * 3 + 2];

        float featr[16];
        #pragma unroll
        for (int e = 0; e < 16; e++) featr[e] = 1.0f;

        const float us[3] = {cx, cy, cx};   // xy:(x,y)  yz:(y,z)  xz:(x,z)
        const float vs[3] = {cy, cz, cz};

        #pragma unroll
        for (int pl = 0; pl < 3; pl++) {
            float fx = (us[pl] + 1.0f) * 0.5f * (float)(HW - 1);
            float fy = (vs[pl] + 1.0f) * 0.5f * (float)(HW - 1);
            float x0f = floorf(fx), y0f = floorf(fy);
            int x0 = (int)x0f, y0 = (int)y0f;
            float wx1 = fx - x0f, wy1 = fy - y0f;
            float wx0 = 1.0f - wx1, wy0 = 1.0f - wy1;
            bool vx0 = (x0 >= 0) && (x0 < HW);
            bool vx1 = (x0 + 1 >= 0) && (x0 + 1 < HW);
            bool vy0 = (y0 >= 0) && (y0 < HW);
            bool vy1 = (y0 + 1 >= 0) && (y0 + 1 < HW);
            float w00 = (vx0 && vy0) ? wx0 * wy0 : 0.0f;
            float w10 = (vx1 && vy0) ? wx1 * wy0 : 0.0f;
            float w01 = (vx0 && vy1) ? wx0 * wy1 : 0.0f;
            float w11 = (vx1 && vy1) ? wx1 * wy1 : 0.0f;
            int x0c = min(max(x0, 0), HW - 1);
            int x1c = min(max(x0 + 1, 0), HW - 1);
            int y0c = min(max(y0, 0), HW - 1);
            int y1c = min(max(y0 + 1, 0), HW - 1);

            const float* base = g_planesT + pl * (HW * HW * C_DIM) + ch0;
            const float4* p00 = (const float4*)(base + (y0c * HW + x0c) * C_DIM);
            const float4* p10 = (const float4*)(base + (y0c * HW + x1c) * C_DIM);
            const float4* p01 = (const float4*)(base + (y1c * HW + x0c) * C_DIM);
            const float4* p11 = (const float4*)(base + (y1c * HW + x1c) * C_DIM);

            #pragma unroll
            for (int cc = 0; cc < 4; cc++) {
                float4 a = p00[cc], b = p10[cc], d = p01[cc], e = p11[cc];
                featr[cc * 4 + 0] *= w00 * a.x + w10 * b.x + w01 * d.x + w11 * e.x;
                featr[cc * 4 + 1] *= w00 * a.y + w10 * b.y + w01 * d.y + w11 * e.y;
                featr[cc * 4 + 2] *= w00 * a.z + w10 * b.z + w01 * d.z + w11 * e.z;
                featr[cc * 4 + 3] *= w00 * a.w + w10 * b.w + w01 * d.w + w11 * e.w;
            }
        }

        #pragma unroll
        for (int e = 0; e < 16; e++)
            Fs[(ch0 + e) * 132 + p] = featr[e];   // stride-1 across warp lanes
    }
    __syncthreads();

    // ---- layer 1: H[o][p] = relu(sum_c F[c][p]*W1[o][c] + b1[o]) ------------
    // accp[d][i]: unit 4ty+d, point-pair i (pairs: {4tx,4tx+1},{4tx+2,4tx+3},
    //             {64+4tx,64+4tx+1},{64+4tx+2,64+4tx+3})
    unsigned long long accp[4][4];
    #pragma unroll
    for (int d = 0; d < 4; d++)
        #pragma unroll
        for (int i = 0; i < 4; i++) accp[d][i] = 0ull;

    #pragma unroll 4
    for (int c = 0; c < 64; c++) {
        ulonglong2 aL = *(const ulonglong2*)&Fs[c * 132 + 4 * tx];
        ulonglong2 aH = *(const ulonglong2*)&Fs[c * 132 + 64 + 4 * tx];
        unsigned long long A[4] = {aL.x, aL.y, aH.x, aH.y};
        #pragma unroll
        for (int d = 0; d < 4; d++) {
            unsigned long long bp = bcast2(W1s[(4 * ty + d) * 65 + c]);
            #pragma unroll
            for (int i = 0; i < 4; i++)
                accp[d][i] = ffma2(A[i], bp, accp[d][i]);
        }
    }
    #pragma unroll
    for (int d = 0; d < 4; d++) {
        int o = 4 * ty + d;
        float bb = b1s[o];
        float v[8];
        #pragma unroll
        for (int i = 0; i < 4; i++) {
            float lo, hi;
            unpack2(accp[d][i], lo, hi);
            v[2 * i]     = fmaxf(lo + bb, 0.0f);
            v[2 * i + 1] = fmaxf(hi + bb, 0.0f);
        }
        *(float4*)&Hs[o * 132 + 4 * tx]      = make_float4(v[0], v[1], v[2], v[3]);
        *(float4*)&Hs[o * 132 + 64 + 4 * tx] = make_float4(v[4], v[5], v[6], v[7]);
    }
    __syncthreads();   // Hs written; region A (W1s) now dead

    // ---- layer 2: two 64-k stages through W2s ------------------------------
    #pragma unroll
    for (int d = 0; d < 4; d++)
        #pragma unroll
        for (int i = 0; i < 4; i++) accp[d][i] = 0ull;

    for (int half = 0; half < 2; half++) {
        // stage W2[:, half*64 .. half*64+63] in o-major pad-65 layout
        for (int i = tid; i < 128 * 64; i += TPB) {
            int o = i >> 6, kk = i & 63;
            W2s[o * 65 + kk] = w2[o * 128 + half * 64 + kk]; // contiguous rows
        }
        __syncthreads();

        const int kbase = half * 64;
        #pragma unroll 4
        for (int kk = 0; kk < 64; kk++) {
            int k = kbase + kk;
            ulonglong2 aL = *(const ulonglong2*)&Hs[k * 132 + 4 * tx];
            ulonglong2 aH = *(const ulonglong2*)&Hs[k * 132 + 64 + 4 * tx];
            unsigned long long A[4] = {aL.x, aL.y, aH.x, aH.y};
            #pragma unroll
            for (int d = 0; d < 4; d++) {
                unsigned long long bp = bcast2(W2s[(4 * ty + d) * 65 + kk]);
                #pragma unroll
                for (int i = 0; i < 4; i++)
                    accp[d][i] = ffma2(A[i], bp, accp[d][i]);
            }
        }
        __syncthreads();   // done with this W2 stage before overwriting
    }

    // ---- layer 2 relu + layer 3 partial dot --------------------------------
    float pout[8];
    #pragma unroll
    for (int i = 0; i < 8; i++) pout[i] = 0.0f;
    #pragma unroll
    for (int d = 0; d < 4; d++) {
        int o = 4 * ty + d;
        float bb = b2s[o];
        float wv = w3s[o];
        #pragma unroll
        for (int i = 0; i < 4; i++) {
            float lo, hi;
            unpack2(accp[d][i], lo, hi);
            pout[2 * i]     += fmaxf(lo + bb, 0.0f) * wv;
            pout[2 * i + 1] += fmaxf(hi + bb, 0.0f) * wv;
        }
    }

    // reduce 32 partials per point via region A
    // point indices for pout[j]: j<4 -> 4tx+j ; j>=4 -> 64+4tx+(j-4)
    #pragma unroll
    for (int j = 0; j < 8; j++) {
        int p = (j < 4) ? (4 * tx + j) : (64 + 4 * tx + (j - 4));
        red[p * 33 + ty] = pout[j];
    }
    __syncthreads();

    if (tid < PTS_PER_BLK) {
        float s = 0.0f;
        #pragma unroll
        for (int j = 0; j < 32; j++) s += red[tid * 33 + j];
        out[blockIdx.x * PTS_PER_BLK + tid] = s + b3[0];
    }
}

extern "C" void kernel_launch(void* const* d_in, const int* in_sizes, int n_in,
                              void* d_out, int out_size) {
    const float* coords = (const float*)d_in[0];
    const float* pxy    = (const float*)d_in[1];
    const float* pyz    = (const float*)d_in[2];
    const float* pxz    = (const float*)d_in[3];
    const float* w1     = (const float*)d_in[4];
    const float* b1     = (const float*)d_in[5];
    const float* w2     = (const float*)d_in[6];
    const float* b2     = (const float*)d_in[7];
    const float* w3     = (const float*)d_in[8];
    const float* b3     = (const float*)d_in[9];
    float* out = (float*)d_out;

    const int M = in_sizes[0] / 3;   // 1048576

    transpose_planes_k<<<(3 * HW * HW * C_DIM + 255) / 256, 256>>>(pxy, pyz, pxz);

    const size_t smem_bytes = SMEM_FL * sizeof(float);  // 136,192 B
    cudaFuncSetAttribute(fused_k, cudaFuncAttributeMaxDynamicSharedMemorySize,
                         (int)smem_bytes);
    fused_k<<<M / PTS_PER_BLK, TPB, smem_bytes>>>(coords, w1, b1, w2, b2, w3, b3, out);
}